// round 14
// baseline (speedup 1.0000x reference)
#include <cuda_runtime.h>
#include <cuda_bf16.h>
#include <cstdint>
#include <math.h>

// Problem constants (fixed by setup_inputs)
#define BB 64
#define TT 1024
#define VV 512
#define SS 128
#define LL 257            // 2*S + 1 extended states
#define GSTRIDE 132       // padded row stride (132 floats = 528B, 16B-aligned)
#define NEGF (-1e30f)
#define PF   6            // cp.async prefetch depth (rows ahead)
#define RING 8            // ring slots (power of 2, > PF+1)
#define LOG2E 1.4426950408889634f
#define LN2   0.6931471805599453f

// Scratch: gathered log2-probs  g[b,t,j] = (logits[b,t,sym_j]-lse(b,t))*log2e
// j=0 -> blank(0), j=1..128 -> target symbols.
__device__ float g_lp[(size_t)BB * TT * GSTRIDE];   // ~34.6 MB
__device__ float g_partial[BB];

// ---------------------------------------------------------------------------
// Phase 1: per-row logsumexp over V=512 + gather of 129 symbol log-probs,
// pre-scaled to log2 domain. One warp per (b,t) row. (~22us, near HBM bound.)
// ---------------------------------------------------------------------------
__global__ __launch_bounds__(256) void lse_gather_kernel(
    const float* __restrict__ logits,      // [B,T,V]
    const int*   __restrict__ in_len,      // [B]
    const int*   __restrict__ tgt)         // [B,S]
{
    int gwarp = (blockIdx.x * blockDim.x + threadIdx.x) >> 5;
    int lane  = threadIdx.x & 31;
    if (gwarp >= BB * TT) return;

    int b = gwarp >> 10;          // / TT
    int t = gwarp & (TT - 1);
    if (t >= in_len[b]) return;   // frames past utterance length never read

    const float4* row4 = (const float4*)(logits + (size_t)gwarp * VV);

    float4 v[4];
    float mx = -INFINITY;
#pragma unroll
    for (int i = 0; i < 4; i++) {
        v[i] = row4[lane + 32 * i];
        mx = fmaxf(mx, fmaxf(fmaxf(v[i].x, v[i].y), fmaxf(v[i].z, v[i].w)));
    }
#pragma unroll
    for (int o = 16; o > 0; o >>= 1)
        mx = fmaxf(mx, __shfl_xor_sync(0xFFFFFFFFu, mx, o));

    float sum = 0.f;
#pragma unroll
    for (int i = 0; i < 4; i++) {
        sum += __expf(v[i].x - mx) + __expf(v[i].y - mx) +
               __expf(v[i].z - mx) + __expf(v[i].w - mx);
    }
#pragma unroll
    for (int o = 16; o > 0; o >>= 1)
        sum += __shfl_xor_sync(0xFFFFFFFFu, sum, o);

    float lse = mx + __logf(sum);

    const float* rowf = logits + (size_t)gwarp * VV;
    const int*   tb   = tgt + b * SS;
    float*       out  = g_lp + (size_t)gwarp * GSTRIDE;
#pragma unroll
    for (int j = lane; j < SS + 1; j += 32) {
        int sym = (j == 0) ? 0 : tb[j - 1];
        out[j] = (rowf[sym] - lse) * LOG2E;   // log2 domain
    }
}

// ---------------------------------------------------------------------------
// Phase 2: CTC alpha recursion in log2 domain. One CTA per batch, 288 threads
// (9 warps), one barrier per step.
//   tid 0..128   (warps 0-4 head): even state 2i  -> lse2 (never skips)
//   tid 129..159 (warp 4 tail)  : staging lanes, 16B cp.async ring
//   tid 160..287 (warps 5-8)    : odd state 2i+1 -> lse3
// Exchange via shared: eesh[i]=e_i, oesh[i+1]=o_i (guard oesh[0]=NEG).
// ---------------------------------------------------------------------------
__device__ __forceinline__ void cp_async_16(unsigned int dst_smem, const float* src)
{
    asm volatile("cp.async.ca.shared.global [%0], [%1], 16;\n"
                 :: "r"(dst_smem), "l"(src));
}
__device__ __forceinline__ void cp_commit()
{
    asm volatile("cp.async.commit_group;\n");
}
__device__ __forceinline__ void cp_wait_pf()
{
    asm volatile("cp.async.wait_group %0;\n" :: "n"(PF));
}
__device__ __forceinline__ float ex2f(float x)
{
    float r; asm("ex2.approx.ftz.f32 %0, %1;" : "=f"(r) : "f"(x)); return r;
}
__device__ __forceinline__ float lg2f(float x)
{
    float r; asm("lg2.approx.ftz.f32 %0, %1;" : "=f"(r) : "f"(x)); return r;
}

__global__ __launch_bounds__(288) void ctc_alpha_kernel(
    const int* __restrict__ in_len,
    const int* __restrict__ tgt,
    const int* __restrict__ tgt_len)
{
    const int b   = blockIdx.x;
    const int tid = threadIdx.x;

    const bool evenT   = (tid <= 128);                 // state 2*tid
    const bool loaderT = (tid >= 129 && tid < 160);    // staging lanes
    const bool oddT    = (tid >= 160);                 // state 2*(tid-160)+1
    const int  i       = evenT ? tid : (tid - 160);    // pair index

    __shared__ __align__(16) float shlp[RING][GSTRIDE];
    __shared__ float eesh[2][129];
    __shared__ float oesh[2][130];                     // [0] = NEG guard

    if (tid < 2) { oesh[tid][0] = NEGF; }              // guards both buffers? no:
    if (tid == 0) { oesh[0][0] = NEGF; oesh[1][0] = NEGF; }

    // skip for odd state 2i+1 (label i): i>=1 && tgt[i]!=tgt[i-1]
    bool skip = false;
    if (oddT && i >= 1)
        skip = (tgt[b * SS + i] != tgt[b * SS + i - 1]);

    const float* grow = g_lp + (size_t)b * TT * GSTRIDE;
    const int len = in_len[b];                         // >= 512 here

    // staging: 33 chunks of 16B per row, lanes tid-129 in [0,31)
    unsigned int slot0 = 0;
    if (loaderT)
        slot0 = (unsigned int)__cvta_generic_to_shared(&shlp[0][0]);

    // Prologue: stage rows 1..PF, one commit-group per row
#pragma unroll
    for (int r = 1; r <= PF; r++) {
        if (loaderT) {
            unsigned int dst = slot0 + (unsigned int)(r & (RING - 1)) * (GSTRIDE * 4);
            for (int c = tid - 129; c < 33; c += 31)
                cp_async_16(dst + c * 16, grow + (size_t)r * GSTRIDE + c * 4);
        }
        cp_commit();
    }

    // t = 0 init (log2 domain)
    float e = NEGF, o = NEGF;
    if (tid == 0)   e = grow[0];
    if (tid == 160) o = grow[1];

    int buf = 0;
    for (int t = 1; t < len; t++) {
        int r = t + PF;
        if (loaderT && r < len) {
            unsigned int dst = slot0 + (unsigned int)(r & (RING - 1)) * (GSTRIDE * 4);
            for (int c = tid - 129; c < 33; c += 31)
                cp_async_16(dst + c * 16, grow + (size_t)r * GSTRIDE + c * 4);
        }
        cp_commit();                       // exactly one group per iteration

        if (evenT) eesh[buf][i] = e;
        if (oddT)  oesh[buf][i + 1] = o;
        cp_wait_pf();                      // row t complete (issuing threads)
        __syncthreads();                   // ...and visible to all

        const float* lpr = shlp[t & (RING - 1)];
        if (evenT) {
            float op = oesh[buf][i];       // o_{i-1} (guard at 0)
            float m  = fmaxf(e, op);
            e = m + lg2f(ex2f(e - m) + ex2f(op - m)) + lpr[0];
        }
        if (oddT) {
            float ep = eesh[buf][i];       // e_i (same time step)
            float op = oesh[buf][i];       // o_{i-1}
            float a2 = skip ? op : NEGF;
            float m  = fmaxf(o, fmaxf(ep, a2));
            o = m + lg2f(ex2f(o - m) + ex2f(ep - m) + ex2f(a2 - m)) + lpr[i + 1];
        }
        buf ^= 1;
    }

    // final exchange
    if (evenT) eesh[buf][i] = e;
    if (oddT)  oesh[buf][i + 1] = o;
    __syncthreads();

    if (tid == 0) {
        int tl = tgt_len[b];
        float x = eesh[buf][tl];       // alpha[2*tl]   (even tl)
        float y = oesh[buf][tl];       // alpha[2*tl-1] (odd tl-1)
        float m = fmaxf(x, y);
        float ll2 = m + lg2f(ex2f(x - m) + ex2f(y - m));
        float loss = -ll2 * LN2;       // back to natural log
        if (loss > 1e29f) loss = 0.f;  // zero_infinity
        g_partial[b] = loss;
    }
}

// ---------------------------------------------------------------------------
// Phase 3: deterministic reduction of 64 per-batch losses -> scalar
// ---------------------------------------------------------------------------
__global__ void reduce_loss_kernel(float* __restrict__ out)
{
    int l = threadIdx.x;                   // 32 threads
    float v = g_partial[l] + g_partial[l + 32];
#pragma unroll
    for (int o = 16; o > 0; o >>= 1)
        v += __shfl_xor_sync(0xFFFFFFFFu, v, o);
    if (l == 0) out[0] = v;
}

// ---------------------------------------------------------------------------
extern "C" void kernel_launch(void* const* d_in, const int* in_sizes, int n_in,
                              void* d_out, int out_size)
{
    const float* logits  = (const float*)d_in[0];   // [B,T,V] fp32
    const int*   in_len  = (const int*)d_in[1];     // [B]
    const int*   tgt     = (const int*)d_in[2];     // [B,S]
    const int*   tgt_len = (const int*)d_in[3];     // [B]
    float*       out     = (float*)d_out;

    lse_gather_kernel<<<(BB * TT) / 8, 256>>>(logits, in_len, tgt);
    ctc_alpha_kernel<<<BB, 288>>>(in_len, tgt, tgt_len);
    reduce_loss_kernel<<<1, 32>>>(out);
}

// round 16
// speedup vs baseline: 1.8710x; 1.8710x over previous
#include <cuda_runtime.h>
#include <cuda_bf16.h>
#include <cstdint>
#include <math.h>

// Problem constants (fixed by setup_inputs)
#define BB 64
#define TT 1024
#define VV 512
#define SS 128
#define LL 257            // 2*S + 1 extended states
#define GSTRIDE 132       // padded row stride for gathered log-probs
#define NEGF (-1e30f)
#define PF   6            // cp.async prefetch depth (rows ahead)
#define RING 8            // ring slots (power of 2, > PF+1)
#define LOG2E 1.4426950408889634f
#define LN2   0.6931471805599453f

// Scratch: gathered log2-probs  g[b,t,j] = (logits[b,t,sym_j]-lse(b,t))*log2e
// j=0 -> blank(0), j=1..128 -> target symbols.
__device__ float g_lp[(size_t)BB * TT * GSTRIDE];   // ~34.6 MB
__device__ float g_partial[BB];

// ---------------------------------------------------------------------------
// Phase 1: per-row logsumexp over V=512 + gather of 129 symbol log-probs,
// pre-scaled to log2 domain. One warp per (b,t) row. (~22us, near HBM bound.)
// ---------------------------------------------------------------------------
__global__ __launch_bounds__(256) void lse_gather_kernel(
    const float* __restrict__ logits,      // [B,T,V]
    const int*   __restrict__ in_len,      // [B]
    const int*   __restrict__ tgt)         // [B,S]
{
    int gwarp = (blockIdx.x * blockDim.x + threadIdx.x) >> 5;
    int lane  = threadIdx.x & 31;
    if (gwarp >= BB * TT) return;

    int b = gwarp >> 10;          // / TT
    int t = gwarp & (TT - 1);
    if (t >= in_len[b]) return;   // frames past utterance length never read

    const float4* row4 = (const float4*)(logits + (size_t)gwarp * VV);

    float4 v[4];
    float mx = -INFINITY;
#pragma unroll
    for (int i = 0; i < 4; i++) {
        v[i] = row4[lane + 32 * i];
        mx = fmaxf(mx, fmaxf(fmaxf(v[i].x, v[i].y), fmaxf(v[i].z, v[i].w)));
    }
#pragma unroll
    for (int o = 16; o > 0; o >>= 1)
        mx = fmaxf(mx, __shfl_xor_sync(0xFFFFFFFFu, mx, o));

    float sum = 0.f;
#pragma unroll
    for (int i = 0; i < 4; i++) {
        sum += __expf(v[i].x - mx) + __expf(v[i].y - mx) +
               __expf(v[i].z - mx) + __expf(v[i].w - mx);
    }
#pragma unroll
    for (int o = 16; o > 0; o >>= 1)
        sum += __shfl_xor_sync(0xFFFFFFFFu, sum, o);

    float lse = mx + __logf(sum);

    const float* rowf = logits + (size_t)gwarp * VV;
    const int*   tb   = tgt + b * SS;
    float*       out  = g_lp + (size_t)gwarp * GSTRIDE;
#pragma unroll
    for (int j = lane; j < SS + 1; j += 32) {
        int sym = (j == 0) ? 0 : tb[j - 1];
        out[j] = (rowf[sym] - lse) * LOG2E;   // log2 domain
    }
}

// ---------------------------------------------------------------------------
// Phase 2: CTC alpha recursion (log2 domain). One CTA per batch element, one
// thread per extended state (R7 structure — proven fastest). lp rows staged
// PF steps ahead via cp.async ring; 1 barrier per step; unroll x2 for
// compile-time buffer parity.
// ---------------------------------------------------------------------------
__device__ __forceinline__ void cp_async_f32(unsigned int dst_smem, const float* src)
{
    asm volatile("cp.async.ca.shared.global [%0], [%1], 4;\n"
                 :: "r"(dst_smem), "l"(src));
}
__device__ __forceinline__ void cp_commit()
{
    asm volatile("cp.async.commit_group;\n");
}
__device__ __forceinline__ void cp_wait_pf()
{
    asm volatile("cp.async.wait_group %0;\n" :: "n"(PF));
}
__device__ __forceinline__ float ex2f(float x)
{
    float r; asm("ex2.approx.ftz.f32 %0, %1;" : "=f"(r) : "f"(x)); return r;
}
__device__ __forceinline__ float lg2f(float x)
{
    float r; asm("lg2.approx.ftz.f32 %0, %1;" : "=f"(r) : "f"(x)); return r;
}

// log2-domain lse3 via 3-sort: the max term is exactly 2^0, so only 2 ex2.
__device__ __forceinline__ float lse3_l2(float a, float a1, float a2, float lp)
{
    float hi1 = fmaxf(a, a1), lo1 = fminf(a, a1);
    float m   = fmaxf(hi1, a2);
    float mid = fmaxf(lo1, fminf(hi1, a2));
    float lo  = fminf(lo1, a2);
    return m + lg2f(1.0f + ex2f(mid - m) + ex2f(lo - m)) + lp;
}

__global__ __launch_bounds__(288) void ctc_alpha_kernel(
    const int* __restrict__ in_len,
    const int* __restrict__ tgt,
    const int* __restrict__ tgt_len)
{
    const int b = blockIdx.x;
    const int s = threadIdx.x;
    const bool active = (s < LL);
    const bool loader = (s < SS + 1);   // threads 0..128 stage lp rows

    // sh[.][0..1] are the s=-2,-1 guards; real state s lives at index s+2
    __shared__ float sh[2][LL + 2];
    __shared__ float shlp[RING][GSTRIDE];
    if (s < 2) { sh[0][s] = NEGF; sh[1][s] = NEGF; }

    // column in gathered row: even state -> blank (j=0), odd state s -> (s+1)/2
    const int col = (s & 1) ? ((s + 1) >> 1) : 0;

    bool skip = false;
    if (active && (s & 1) && s >= 3) {
        int k = (s - 1) >> 1;
        skip = (tgt[b * SS + k] != tgt[b * SS + k - 1]);
    }

    const float* grow = g_lp + (size_t)b * TT * GSTRIDE;
    const int len = in_len[b];           // len >= 512 for this problem

    unsigned int slotb = 0;
    if (loader)
        slotb = (unsigned int)__cvta_generic_to_shared(&shlp[0][s]);

    // Prologue: stage rows 1..PF (group g <-> row g)
#pragma unroll
    for (int r = 1; r <= PF; r++) {
        if (loader)
            cp_async_f32(slotb + (unsigned int)(r & (RING - 1)) * (GSTRIDE * 4),
                         grow + (size_t)r * GSTRIDE + s);
        cp_commit();
    }

    // t = 0 init (log2 domain)
    float a = NEGF;
    if (s < 2) a = grow[col];

    // strength-reduced cp.async source: points at row t+PF for iteration t
    const float* gsrc = grow + (size_t)(1 + PF) * GSTRIDE + s;

#define STEP_BODY(T, BUF)                                                     \
    {                                                                         \
        int r_ = (T) + PF;                                                    \
        if (loader && r_ < len)                                               \
            cp_async_f32(slotb + (unsigned int)(r_ & (RING - 1)) * (GSTRIDE * 4), \
                         gsrc);                                               \
        gsrc += GSTRIDE;                                                      \
        cp_commit();                      /* one group per step */            \
        if (active) sh[BUF][s + 2] = a;                                       \
        cp_wait_pf();                     /* row T complete (issuers) */      \
        __syncthreads();                  /* ...visible to all */             \
        if (active) {                                                         \
            const float* lpr = shlp[(T) & (RING - 1)];                        \
            float a1 = sh[BUF][s + 1];                                        \
            float a2 = skip ? sh[BUF][s] : NEGF;                              \
            a = lse3_l2(a, a1, a2, lpr[col]);                                 \
        }                                                                     \
    }

    int t = 1;
    for (; t + 1 < len; t += 2) {        // buffer parity compile-time
        STEP_BODY(t, 0);
        STEP_BODY(t + 1, 1);
    }
    if (t < len) {                        // at most one tail step
        STEP_BODY(t, 0);
    }
#undef STEP_BODY

    // final exchange through buffer 0
    if (active) sh[0][s + 2] = a;
    __syncthreads();

    if (s == 0) {
        int e = 2 * tgt_len[b];
        float x = sh[0][e + 2];       // alpha[2*tl]
        float y = sh[0][e + 1];       // alpha[2*tl - 1]
        float m = fmaxf(x, y);
        float ll2 = m + lg2f(ex2f(x - m) + ex2f(y - m));
        float loss = -ll2 * LN2;      // back to natural log
        if (loss > 1e29f) loss = 0.f; // zero_infinity
        g_partial[b] = loss;
    }
}

// ---------------------------------------------------------------------------
// Phase 3: deterministic reduction of 64 per-batch losses -> scalar
// ---------------------------------------------------------------------------
__global__ void reduce_loss_kernel(float* __restrict__ out)
{
    int l = threadIdx.x;                   // 32 threads
    float v = g_partial[l] + g_partial[l + 32];
#pragma unroll
    for (int o = 16; o > 0; o >>= 1)
        v += __shfl_xor_sync(0xFFFFFFFFu, v, o);
    if (l == 0) out[0] = v;
}

// ---------------------------------------------------------------------------
extern "C" void kernel_launch(void* const* d_in, const int* in_sizes, int n_in,
                              void* d_out, int out_size)
{
    const float* logits  = (const float*)d_in[0];   // [B,T,V] fp32
    const int*   in_len  = (const int*)d_in[1];     // [B]
    const int*   tgt     = (const int*)d_in[2];     // [B,S]
    const int*   tgt_len = (const int*)d_in[3];     // [B]
    float*       out     = (float*)d_out;

    lse_gather_kernel<<<(BB * TT) / 8, 256>>>(logits, in_len, tgt);
    ctc_alpha_kernel<<<BB, 288>>>(in_len, tgt, tgt_len);
    reduce_loss_kernel<<<1, 32>>>(out);
}